// round 7
// baseline (speedup 1.0000x reference)
#include <cuda_runtime.h>

// kmeans assignment: y[i] = argmin_c (x2 + p2) - 2*(x.p), labels as f32.
// R7: packed fp32 math via PTX fma.rn.f32x2 (FFMA2). Each lane rounds
// exactly like scalar __fmaf_rn, so the fp32 chain (and rel_err) is
// bit-identical to R6; fma-pipe issue count halves.
// Points packed in pairs: lane0 = pt0, lane1 = pt1. Phi stored in smem
// pre-duplicated (p,p) so the inner loop needs no pack instructions.

#define TPB   384
#define DD    50
#define CHUNK 64
#define PPT   2
#define PTS_PER_BLOCK (TPB * PPT)
#define FLT_BIG 3.402823466e38f
#define MAXD  128

typedef unsigned long long u64;

__device__ __forceinline__ u64 pack2(float lo, float hi) {
    u64 r;
    asm("mov.b64 %0, {%1, %2};" : "=l"(r) : "f"(lo), "f"(hi));
    return r;
}
__device__ __forceinline__ void unpack2(u64 v, float& lo, float& hi) {
    asm("mov.b64 {%0, %1}, %2;" : "=f"(lo), "=f"(hi) : "l"(v));
}
__device__ __forceinline__ void fma2(u64& acc, u64 a, u64 b) {
    asm("fma.rn.f32x2 %0, %1, %2, %0;" : "+l"(acc) : "l"(a), "l"(b));
}

// ------------------------- fast path: D = 50 -------------------------
__global__ __launch_bounds__(TPB)
void kmeans_fast50(const float* __restrict__ X,
                   const float* __restrict__ Phi,
                   float* __restrict__ out, int n, int C)
{
    __shared__ __align__(16) u64 sPhiD[DD * CHUNK];  // (p,p) dup pairs, 25,600 B
    __shared__ float sP2[CHUNK];

    const int base = blockIdx.x * PTS_PER_BLOCK;
    const int pt0  = base + threadIdx.x;
    const int pt1  = pt0 + TPB;

    // Load both points, compute x2 (rounded square + sequential add,
    // k ascending -- same chain as R6), then pack points into pairs.
    u64   xp[DD];
    float x2a = 0.f, x2b = 0.f;
    {
        const long long r0 = (long long)(pt0 < n ? pt0 : 0) * DD;
        const long long r1 = (long long)(pt1 < n ? pt1 : 0) * DD;
        const float2* a = reinterpret_cast<const float2*>(X + r0);
        const float2* b = reinterpret_cast<const float2*>(X + r1);
        #pragma unroll
        for (int j = 0; j < DD / 2; ++j) {
            const float2 va = a[j];
            const float2 vb = b[j];
            x2a = __fadd_rn(x2a, __fmul_rn(va.x, va.x));
            x2b = __fadd_rn(x2b, __fmul_rn(vb.x, vb.x));
            x2a = __fadd_rn(x2a, __fmul_rn(va.y, va.y));
            x2b = __fadd_rn(x2b, __fmul_rn(vb.y, vb.y));
            xp[2*j]   = pack2(va.x, vb.x);
            xp[2*j+1] = pack2(va.y, vb.y);
        }
    }

    float best0 = FLT_BIG, best1 = FLT_BIG;
    int   bi0 = 0, bi1 = 0;

    #pragma unroll 1
    for (int cb = 0; cb < C; cb += CHUNK) {
        const int cc = (C - cb < CHUNK) ? (C - cb) : CHUNK;

        __syncthreads();
        // Transposed + duplicated fill: sPhiD[d*CHUNK + c] = (Phi[cb+c][d],) x2
        for (int i = threadIdx.x; i < cc * DD; i += TPB) {
            const int c = i / DD;
            const int d = i - c * DD;
            const float v = Phi[(long long)(cb + c) * DD + d];
            sPhiD[d * CHUNK + c] = pack2(v, v);
        }
        __syncthreads();
        // p2: rounded square + sequential add, d ascending (same chain).
        if (threadIdx.x < cc) {
            float s = 0.f;
            #pragma unroll
            for (int d = 0; d < DD; ++d) {
                const float v = ((const float*)&sPhiD[d * CHUNK + threadIdx.x])[0];
                s = __fadd_rn(s, __fmul_rn(v, v));
            }
            sP2[threadIdx.x] = s;
        }
        __syncthreads();

        int c = 0;
        #pragma unroll 1
        for (; c + 4 <= cc; c += 4) {
            u64 acc0 = 0ull, acc1 = 0ull, acc2 = 0ull, acc3 = 0ull;
            const ulonglong2* pD = reinterpret_cast<const ulonglong2*>(sPhiD + c);
            #pragma unroll
            for (int d = 0; d < DD; ++d) {
                const ulonglong2 q0 = pD[d * (CHUNK / 2)];      // (c,c),(c+1,c+1)
                const ulonglong2 q1 = pD[d * (CHUNK / 2) + 1];  // (c+2..),(c+3..)
                fma2(acc0, xp[d], q0.x);   // sequential fma over d: same chain
                fma2(acc1, xp[d], q0.y);
                fma2(acc2, xp[d], q1.x);
                fma2(acc3, xp[d], q1.y);
            }
            float a00, a10, a01, a11, a02, a12, a03, a13;
            unpack2(acc0, a00, a10);
            unpack2(acc1, a01, a11);
            unpack2(acc2, a02, a12);
            unpack2(acc3, a03, a13);
            const float q0 = sP2[c], q1 = sP2[c+1], q2 = sP2[c+2], q3 = sP2[c+3];
            // d2 = (x2 + p2) - (2 * mm): identical op sequence to R6.
            const float s00 = __fsub_rn(__fadd_rn(x2a, q0), __fmul_rn(2.f, a00));
            const float s01 = __fsub_rn(__fadd_rn(x2a, q1), __fmul_rn(2.f, a01));
            const float s02 = __fsub_rn(__fadd_rn(x2a, q2), __fmul_rn(2.f, a02));
            const float s03 = __fsub_rn(__fadd_rn(x2a, q3), __fmul_rn(2.f, a03));
            const float s10 = __fsub_rn(__fadd_rn(x2b, q0), __fmul_rn(2.f, a10));
            const float s11 = __fsub_rn(__fadd_rn(x2b, q1), __fmul_rn(2.f, a11));
            const float s12 = __fsub_rn(__fadd_rn(x2b, q2), __fmul_rn(2.f, a12));
            const float s13 = __fsub_rn(__fadd_rn(x2b, q3), __fmul_rn(2.f, a13));
            const int g = cb + c;
            if (s00 < best0) { best0 = s00; bi0 = g;     }
            if (s01 < best0) { best0 = s01; bi0 = g + 1; }
            if (s02 < best0) { best0 = s02; bi0 = g + 2; }
            if (s03 < best0) { best0 = s03; bi0 = g + 3; }
            if (s10 < best1) { best1 = s10; bi1 = g;     }
            if (s11 < best1) { best1 = s11; bi1 = g + 1; }
            if (s12 < best1) { best1 = s12; bi1 = g + 2; }
            if (s13 < best1) { best1 = s13; bi1 = g + 3; }
        }
        for (; c < cc; ++c) {   // tail if C % 4 != 0 (unused for C=256)
            u64 acc = 0ull;
            #pragma unroll
            for (int d = 0; d < DD; ++d)
                fma2(acc, xp[d], sPhiD[d * CHUNK + c]);
            float a0, a1;
            unpack2(acc, a0, a1);
            const float q  = sP2[c];
            const float s0 = __fsub_rn(__fadd_rn(x2a, q), __fmul_rn(2.f, a0));
            const float s1 = __fsub_rn(__fadd_rn(x2b, q), __fmul_rn(2.f, a1));
            if (s0 < best0) { best0 = s0; bi0 = cb + c; }
            if (s1 < best1) { best1 = s1; bi1 = cb + c; }
        }
    }

    if (pt0 < n) out[pt0] = (float)bi0;   // float32 labels
    if (pt1 < n) out[pt1] = (float)bi1;
}

// --------------------- generic fallback: any D, C ---------------------
__global__ __launch_bounds__(256)
void kmeans_generic(const float* __restrict__ X,
                    const float* __restrict__ Phi,
                    float* __restrict__ out, int n, int D, int C)
{
    for (int idx = blockIdx.x * blockDim.x + threadIdx.x; idx < n;
         idx += gridDim.x * blockDim.x) {
        float xr[MAXD];
        const int Dc = (D < MAXD) ? D : MAXD;
        const long long row = (long long)idx * D;
        for (int d = 0; d < Dc; ++d) xr[d] = X[row + d];

        float x2 = 0.f;
        for (int d = 0; d < Dc; ++d) x2 = __fadd_rn(x2, __fmul_rn(xr[d], xr[d]));

        float best = FLT_BIG;
        int   bi   = 0;
        for (int c = 0; c < C; ++c) {
            const long long pr = (long long)c * D;
            float mm = 0.f, p2 = 0.f;
            for (int d = 0; d < Dc; ++d) {
                const float pv = __ldg(&Phi[pr + d]);
                mm = __fmaf_rn(xr[d], pv, mm);
                p2 = __fadd_rn(p2, __fmul_rn(pv, pv));
            }
            const float s = __fsub_rn(__fadd_rn(x2, p2), __fmul_rn(2.f, mm));
            if (s < best) { best = s; bi = c; }
        }
        out[idx] = (float)bi;
    }
}

// ------------------------------ launch ------------------------------
extern "C" void kernel_launch(void* const* d_in, const int* in_sizes, int n_in,
                              void* d_out, int out_size)
{
    int iX = 0;
    for (int i = 1; i < n_in; ++i)
        if (in_sizes[i] > in_sizes[iX]) iX = i;
    int iP = (iX == 0) ? (n_in > 1 ? 1 : 0) : 0;
    for (int i = 0; i < n_in; ++i)
        if (i != iX && in_sizes[i] > in_sizes[iP]) iP = i;

    const float* X   = (const float*)d_in[iX];
    const float* Phi = (const float*)d_in[iP];
    float*       out = (float*)d_out;

    const int n = out_size;
    if (n <= 0) return;
    const int D = in_sizes[iX] / n;
    const int C = (D > 0) ? in_sizes[iP] / D : 0;
    if (D <= 0 || C <= 0) return;

    if (D == DD) {
        const int blocks = (n + PTS_PER_BLOCK - 1) / PTS_PER_BLOCK;
        kmeans_fast50<<<blocks, TPB>>>(X, Phi, out, n, C);
    } else {
        int blocks = (n + 255) / 256;
        if (blocks > 65535 * 8) blocks = 65535 * 8;
        kmeans_generic<<<blocks, 256>>>(X, Phi, out, n, D, C);
    }
}